// round 12
// baseline (speedup 1.0000x reference)
#include <cuda_runtime.h>
#include <cuda_bf16.h>
#include <math_constants.h>
#include <climits>
#include <cstdint>

#define BB 512
#define NN 131072
#define DD 512
#define KK 16

#define CAND_CAP 2048
#define SEL_CAP  128
#define THRESH   0.14f
#define EPS_SCR  3e-3f   // >> bf16 screen error (~1.5e-4)
#define SEL_GAP  6e-3f   // screen-value cut below v16_screen

// ---------------------------------------------------------------------------
__device__ __nv_bfloat16  g_mbf[(size_t)NN * DD];
__device__ __nv_bfloat16  g_qbf[(size_t)BB * DD];
__device__ float g_qrs[BB];
__device__ float g_nb[NN];
__device__ int   g_cand[(size_t)BB * CAND_CAP];
__device__ float g_candval[(size_t)BB * CAND_CAP];
__device__ int   g_candcnt[BB];

__device__ __forceinline__ uint32_t smem_u32(const void* p) {
    uint32_t a;
    asm("{ .reg .u64 t; cvta.to.shared.u64 t, %1; cvt.u32.u64 %0, t; }" : "=r"(a) : "l"(p));
    return a;
}
__device__ __forceinline__ void ldmatrix_x4(uint32_t& r0, uint32_t& r1, uint32_t& r2, uint32_t& r3,
                                            uint32_t addr) {
    asm volatile("ldmatrix.sync.aligned.m8n8.x4.shared.b16 {%0,%1,%2,%3}, [%4];"
                 : "=r"(r0), "=r"(r1), "=r"(r2), "=r"(r3) : "r"(addr));
}
__device__ __forceinline__ void mma_bf16(float* c, const uint32_t* a, const uint32_t* b) {
    asm volatile(
        "mma.sync.aligned.m16n8k16.row.col.f32.bf16.bf16.f32 "
        "{%0,%1,%2,%3}, {%4,%5,%6,%7}, {%8,%9}, {%0,%1,%2,%3};"
        : "+f"(c[0]), "+f"(c[1]), "+f"(c[2]), "+f"(c[3])
        : "r"(a[0]), "r"(a[1]), "r"(a[2]), "r"(a[3]), "r"(b[0]), "r"(b[1]));
}
__device__ __forceinline__ void cp_async16(uint32_t smem_addr, const void* gptr) {
    asm volatile("cp.async.cg.shared.global [%0], [%1], 16;" :: "r"(smem_addr), "l"(gptr));
}
__device__ __forceinline__ void cp_commit() {
    asm volatile("cp.async.commit_group;" ::: "memory");
}
template <int N>
__device__ __forceinline__ void cp_wait() {
    asm volatile("cp.async.wait_group %0;" :: "n"(N) : "memory");
}

// ---------------------------------------------------------------------------
// Merged prep: zero counters (block 0) + bf16 conversion + scales for M and Q.
// ---------------------------------------------------------------------------
#define MBLKS (NN / 8)

__global__ void prep_kernel(const float* __restrict__ Q, const float* __restrict__ M,
                            const float* __restrict__ imp) {
    if (blockIdx.x == 0) {
        int t = threadIdx.x;
#pragma unroll
        for (int i = 0; i < BB / 256; ++i) g_candcnt[t + i * 256] = 0;
    }
    const int wrow = blockIdx.x * 8 + (threadIdx.x >> 5);
    const int lane = threadIdx.x & 31;

    const float* src;
    __nv_bfloat16* dst;
    int row;
    bool is_m;
    if (blockIdx.x < MBLKS) {
        row = wrow; is_m = true;
        if (row >= NN) return;
        src = M + (size_t)row * DD;
        dst = g_mbf + (size_t)row * DD;
    } else {
        row = wrow - NN; is_m = false;
        if (row >= BB) return;
        src = Q + (size_t)row * DD;
        dst = g_qbf + (size_t)row * DD;
    }

    const float4* s4 = (const float4*)src;
    float s = 0.0f;
#pragma unroll
    for (int i = 0; i < 4; ++i) {
        float4 f = s4[i * 32 + lane];
        s += f.x * f.x + f.y * f.y + f.z * f.z + f.w * f.w;
        __nv_bfloat162 p0 = __floats2bfloat162_rn(f.x, f.y);
        __nv_bfloat162 p1 = __floats2bfloat162_rn(f.z, f.w);
        uint2 u;
        u.x = *(uint32_t*)&p0;
        u.y = *(uint32_t*)&p1;
        *(uint2*)(dst + (size_t)(i * 32 + lane) * 4) = u;
    }
#pragma unroll
    for (int o = 16; o > 0; o >>= 1) s += __shfl_xor_sync(0xffffffffu, s, o);
    if (lane == 0) {
        float nrm = sqrtf(s);
        if (is_m) g_nb[row] = (1.0f + 0.3f * imp[row]) / nrm;
        else      g_qrs[row] = 1.0f / nrm;
    }
}

// ---------------------------------------------------------------------------
// bf16 HMMA GEMM (NT) + fused threshold-scan epilogue.
// CTA tile 64(B) x 128(N), 2 warps each 64x64 (ratio-4 preserved).
// KBLK=32, 3-stage cp.async, one barrier per kt; 46 KB smem/CTA ->
// 4 independent CTAs per SM (4 pipelines interleave; 64-thread barriers).
// ---------------------------------------------------------------------------
#define BM 64
#define BN 128
#define KBLK 32
#define NKB  (DD / KBLK)   // 16
#define APAD 40
#define STAGES 3
#define ASTG (BM * APAD * 2)   // 5120 B
#define BSTG (BN * APAD * 2)   // 10240 B
#define GEMM_SMEM (STAGES * (ASTG + BSTG))   // 46080 B

__device__ __forceinline__ void issue_stage(uint32_t sA, uint32_t sB,
                                            const __nv_bfloat16* Abase,
                                            const __nv_bfloat16* Bbase,
                                            int kb, int stage, int tid) {
    const uint32_t a0 = sA + (uint32_t)stage * ASTG;
    const uint32_t b0 = sB + (uint32_t)stage * BSTG;
    const int koff = kb * KBLK;
    // A: 64 rows x 4 chunks(16B) = 256 chunks, 4 per thread (64 threads)
#pragma unroll
    for (int i = 0; i < 4; ++i) {
        int idx = tid + i * 64;
        int r = idx >> 2, c = idx & 3;
        cp_async16(a0 + (uint32_t)(r * APAD + c * 8) * 2,
                   Abase + (size_t)r * DD + koff + c * 8);
    }
    // B: 128 rows x 4 chunks = 512 chunks, 8 per thread
#pragma unroll
    for (int i = 0; i < 8; ++i) {
        int idx = tid + i * 64;
        int r = idx >> 2, c = idx & 3;
        cp_async16(b0 + (uint32_t)(r * APAD + c * 8) * 2,
                   Bbase + (size_t)r * DD + koff + c * 8);
    }
    cp_commit();
}

__global__ __launch_bounds__(64, 4)
void gemm_scan_kernel() {
    extern __shared__ __align__(16) char smem[];
    const uint32_t sA = smem_u32(smem);
    const uint32_t sB = sA + STAGES * ASTG;

    const int tid  = threadIdx.x;
    const int wn   = tid >> 5;   // warp 0/1 -> N columns wn*64
    const int lane = tid & 31;

    const int b0 = blockIdx.x * BM;
    const int n0 = blockIdx.y * BN;

    const __nv_bfloat16* Abase = g_qbf + (size_t)b0 * DD;
    const __nv_bfloat16* Bbase = g_mbf + (size_t)n0 * DD;

    float acc[4][8][4];
#pragma unroll
    for (int mt = 0; mt < 4; ++mt)
#pragma unroll
        for (int nt = 0; nt < 8; ++nt)
#pragma unroll
            for (int r = 0; r < 4; ++r) acc[mt][nt][r] = 0.0f;

#pragma unroll
    for (int s = 0; s < STAGES - 1; ++s)
        issue_stage(sA, sB, Abase, Bbase, s, s, tid);

    const int rbase = lane & 15;
    const int colhalf = (lane >> 4) * 8;

    for (int kt = 0; kt < NKB; ++kt) {
        if (kt == NKB - 1) cp_wait<0>();
        else               cp_wait<1>();
        __syncthreads();

        if (kt + STAGES - 1 < NKB)
            issue_stage(sA, sB, Abase, Bbase, kt + STAGES - 1,
                        (kt + STAGES - 1) % STAGES, tid);

        const int cur = kt % STAGES;
        const uint32_t aST = sA + (uint32_t)cur * ASTG;
        const uint32_t bST = sB + (uint32_t)cur * BSTG;

#pragma unroll
        for (int ks = 0; ks < KBLK / 16; ++ks) {
            const int col = ks * 16 + colhalf;
            uint32_t af[4][4];
#pragma unroll
            for (int mt = 0; mt < 4; ++mt) {
                int row = mt * 16 + rbase;
                ldmatrix_x4(af[mt][0], af[mt][1], af[mt][2], af[mt][3],
                            aST + (uint32_t)(row * APAD + col) * 2);
            }
            uint32_t bf[8][2];
#pragma unroll
            for (int ng = 0; ng < 4; ++ng) {
                int row = wn * 64 + ng * 16 + rbase;
                uint32_t r0, r1, r2, r3;
                ldmatrix_x4(r0, r1, r2, r3, bST + (uint32_t)(row * APAD + col) * 2);
                bf[ng * 2 + 0][0] = r0; bf[ng * 2 + 0][1] = r2;
                bf[ng * 2 + 1][0] = r1; bf[ng * 2 + 1][1] = r3;
            }
#pragma unroll
            for (int mt = 0; mt < 4; ++mt)
#pragma unroll
                for (int nt = 0; nt < 8; ++nt)
                    mma_bf16(acc[mt][nt], af[mt], bf[nt]);
        }
    }

    // Epilogue: threshold scan, push (index, screen value)
    const int r0 = lane >> 2;
    const int c0 = (lane & 3) * 2;
#pragma unroll
    for (int mt = 0; mt < 4; ++mt) {
        const int brow0 = b0 + mt * 16 + r0;
        const float q0 = g_qrs[brow0];
        const float q1 = g_qrs[brow0 + 8];
#pragma unroll
        for (int nt = 0; nt < 8; ++nt) {
            const int n = n0 + wn * 64 + nt * 8 + c0;
            const float nb0 = g_nb[n];
            const float nb1 = g_nb[n + 1];
            float v00 = acc[mt][nt][0] * q0 * nb0;
            float v01 = acc[mt][nt][1] * q0 * nb1;
            float v10 = acc[mt][nt][2] * q1 * nb0;
            float v11 = acc[mt][nt][3] * q1 * nb1;
            if (v00 > THRESH) {
                int s = atomicAdd(&g_candcnt[brow0], 1);
                if (s < CAND_CAP) {
                    g_cand[(size_t)brow0 * CAND_CAP + s] = n;
                    g_candval[(size_t)brow0 * CAND_CAP + s] = v00;
                }
            }
            if (v01 > THRESH) {
                int s = atomicAdd(&g_candcnt[brow0], 1);
                if (s < CAND_CAP) {
                    g_cand[(size_t)brow0 * CAND_CAP + s] = n + 1;
                    g_candval[(size_t)brow0 * CAND_CAP + s] = v01;
                }
            }
            if (v10 > THRESH) {
                int s = atomicAdd(&g_candcnt[brow0 + 8], 1);
                if (s < CAND_CAP) {
                    g_cand[(size_t)(brow0 + 8) * CAND_CAP + s] = n;
                    g_candval[(size_t)(brow0 + 8) * CAND_CAP + s] = v10;
                }
            }
            if (v11 > THRESH) {
                int s = atomicAdd(&g_candcnt[brow0 + 8], 1);
                if (s < CAND_CAP) {
                    g_cand[(size_t)(brow0 + 8) * CAND_CAP + s] = n + 1;
                    g_candval[(size_t)(brow0 + 8) * CAND_CAP + s] = v11;
                }
            }
        }
    }
}

// ---------------------------------------------------------------------------
// Finalize: screen-value preselection + exact f32 rescore + certification
// + inline brute-force fallback (flagged only) + inline gather. One launch.
// ---------------------------------------------------------------------------
__global__ void finalize_kernel(const float* __restrict__ Q, const float* __restrict__ M,
                                const float* __restrict__ imp, float* __restrict__ out) {
    const int b = blockIdx.x;
    const int t = threadIdx.x;
    const int w = t >> 5;
    const int lane = t & 31;
    const int raw = g_candcnt[b];
    const int cnt = min(raw, CAND_CAP);

    __shared__ float s_val[CAND_CAP];
    __shared__ int   s_idx[CAND_CAP];
    __shared__ float s_q[DD];
    __shared__ float rv[256];
    __shared__ int   ri[256];
    __shared__ int   s_seln[SEL_CAP];
    __shared__ float s_excl[256];
    __shared__ float e_val[SEL_CAP];
    __shared__ int   e_n[SEL_CAP];
    __shared__ int   s_selcnt;
    __shared__ float s_v16s;
    __shared__ int   s_bad;
    __shared__ int   s_top[KK];

    for (int d = t; d < DD; d += 256) s_q[d] = Q[(size_t)b * DD + d];
    for (int s = t; s < cnt; s += 256) {
        s_val[s] = g_candval[(size_t)b * CAND_CAP + s];
        s_idx[s] = g_cand[(size_t)b * CAND_CAP + s];
    }
    if (t == 0) s_selcnt = 0;
    __syncthreads();

    // qn once (per warp redundant)
    float q2 = 0.0f;
    for (int d = lane; d < DD; d += 32) { float x = s_q[d]; q2 = fmaf(x, x, q2); }
#pragma unroll
    for (int o = 16; o > 0; o >>= 1) q2 += __shfl_xor_sync(0xffffffffu, q2, o);
    const float qn = sqrtf(q2);

    // ---- exact 16th-largest screen value ----
    float lv[KK]; int ls[KK];
#pragma unroll
    for (int i = 0; i < KK; ++i) { lv[i] = -CUDART_INF_F; ls[i] = INT_MAX; }
    for (int s = t; s < cnt; s += 256) {
        float x = s_val[s];
        if (x > lv[KK - 1]) {
            lv[KK - 1] = x; ls[KK - 1] = s;
#pragma unroll
            for (int p = KK - 1; p >= 1; --p) {
                if (lv[p] > lv[p - 1]) {
                    float tv = lv[p]; lv[p] = lv[p - 1]; lv[p - 1] = tv;
                    int   ti = ls[p]; ls[p] = ls[p - 1]; ls[p - 1] = ti;
                }
            }
        }
    }
    for (int round = 0; round < KK; ++round) {
        float bvv = -CUDART_INF_F; int bss = INT_MAX;
#pragma unroll
        for (int j = 0; j < KK; ++j) {
            if (lv[j] > bvv || (lv[j] == bvv && ls[j] < bss)) { bvv = lv[j]; bss = ls[j]; }
        }
        rv[t] = bvv; ri[t] = bss;
        __syncthreads();
        for (int s = 128; s > 0; s >>= 1) {
            if (t < s) {
                float ov = rv[t + s]; int os = ri[t + s];
                if (ov > rv[t] || (ov == rv[t] && os < ri[t])) { rv[t] = ov; ri[t] = os; }
            }
            __syncthreads();
        }
        if (round == KK - 1) {
            if (t == 0) s_v16s = rv[0];
        }
        int wslot = ri[0];
#pragma unroll
        for (int j = 0; j < KK; ++j) {
            if (ls[j] == wslot) { lv[j] = -CUDART_INF_F; ls[j] = INT_MAX; }
        }
        __syncthreads();
    }
    const float thresh2 = s_v16s - SEL_GAP;

    // ---- select survivors; track max excluded screen value ----
    float exl = -CUDART_INF_F;
    for (int s = t; s < cnt; s += 256) {
        if (s_val[s] >= thresh2) {
            int pos = atomicAdd(&s_selcnt, 1);
            if (pos < SEL_CAP) s_seln[pos] = s_idx[s];
        } else {
            exl = fmaxf(exl, s_val[s]);
        }
    }
    s_excl[t] = exl;
    __syncthreads();
    for (int s = 128; s > 0; s >>= 1) {
        if (t < s) s_excl[t] = fmaxf(s_excl[t], s_excl[t + s]);
        __syncthreads();
    }
    const float excl_max = s_excl[0];
    const int selraw = s_selcnt;
    const int nsel = min(selraw, SEL_CAP);

    // ---- exact f32 rescore of survivors (warp per candidate) ----
    for (int s = w; s < nsel; s += 8) {
        const int idx = s_seln[s];
        const float4* m = (const float4*)(M + (size_t)idx * DD);
        float dot = 0.0f, m2 = 0.0f;
#pragma unroll
        for (int i = 0; i < 4; ++i) {
            float4 mv = m[i * 32 + lane];
            const float* qp = &s_q[(i * 32 + lane) * 4];
            dot = fmaf(mv.x, qp[0], dot); dot = fmaf(mv.y, qp[1], dot);
            dot = fmaf(mv.z, qp[2], dot); dot = fmaf(mv.w, qp[3], dot);
            m2  = fmaf(mv.x, mv.x, m2);   m2  = fmaf(mv.y, mv.y, m2);
            m2  = fmaf(mv.z, mv.z, m2);   m2  = fmaf(mv.w, mv.w, m2);
        }
#pragma unroll
        for (int o = 16; o > 0; o >>= 1) {
            dot += __shfl_xor_sync(0xffffffffu, dot, o);
            m2  += __shfl_xor_sync(0xffffffffu, m2, o);
        }
        if (lane == 0) {
            float den = fmaxf(qn * sqrtf(m2), 1e-8f);
            e_val[s] = (dot / den) * (1.0f + 0.3f * imp[idx]);
            e_n[s] = idx;
        }
    }
    __syncthreads();

    if (t == 0) {
        float bv[KK]; int bi[KK];
#pragma unroll
        for (int i = 0; i < KK; ++i) { bv[i] = -CUDART_INF_F; bi[i] = INT_MAX; }
        for (int s = 0; s < nsel; ++s) {
            float val = e_val[s]; int id = e_n[s];
            if (val > bv[KK - 1] || (val == bv[KK - 1] && id < bi[KK - 1])) {
                bv[KK - 1] = val; bi[KK - 1] = id;
                for (int p = KK - 1; p >= 1; --p) {
                    bool sw = (bv[p] > bv[p - 1]) || (bv[p] == bv[p - 1] && bi[p] < bi[p - 1]);
                    if (!sw) break;
                    float tv = bv[p]; bv[p] = bv[p - 1]; bv[p - 1] = tv;
                    int   ti = bi[p]; bi[p] = bi[p - 1]; bi[p - 1] = ti;
                }
            }
        }
        bool bad = (raw < KK) || (raw > CAND_CAP) || (selraw > SEL_CAP) || (nsel < KK) ||
                   (bv[KK - 1] < THRESH + EPS_SCR) ||
                   (cnt > nsel && bv[KK - 1] < excl_max + EPS_SCR);
        s_bad = bad ? 1 : 0;
        for (int r = 0; r < KK; ++r) {
            out[b * KK + r] = bv[r];
            s_top[r] = bi[r];
        }
    }
    __syncthreads();

    // ---- brute-force fallback (only if certification failed) ----
    if (s_bad) {
        float v[KK]; int ix[KK];
#pragma unroll
        for (int i = 0; i < KK; ++i) { v[i] = -CUDART_INF_F; ix[i] = INT_MAX; }
        for (int n = t; n < NN; n += 256) {
            const float* m = M + (size_t)n * DD;
            float dot = 0.0f, m2 = 0.0f;
            for (int d = 0; d < DD; ++d) {
                float a = s_q[d], bb = m[d];
                dot = fmaf(a, bb, dot); m2 = fmaf(bb, bb, m2);
            }
            float den = fmaxf(qn * sqrtf(m2), 1e-8f);
            float val = (dot / den) * (1.0f + 0.3f * imp[n]);
            if (val > v[KK - 1]) {
                v[KK - 1] = val; ix[KK - 1] = n;
                for (int p = KK - 1; p >= 1; --p) {
                    if (v[p] > v[p - 1]) {
                        float tv = v[p]; v[p] = v[p - 1]; v[p - 1] = tv;
                        int ti = ix[p]; ix[p] = ix[p - 1]; ix[p - 1] = ti;
                    }
                }
            }
        }
        for (int round = 0; round < KK; ++round) {
            float bvv = -CUDART_INF_F; int bii = INT_MAX;
#pragma unroll
            for (int j = 0; j < KK; ++j) {
                bool better = (v[j] > bvv) || (v[j] == bvv && ix[j] < bii);
                if (better) { bvv = v[j]; bii = ix[j]; }
            }
            rv[t] = bvv; ri[t] = bii;
            __syncthreads();
            for (int s = 128; s > 0; s >>= 1) {
                if (t < s) {
                    float ov2 = rv[t + s]; int oi2 = ri[t + s];
                    if (ov2 > rv[t] || (ov2 == rv[t] && oi2 < ri[t])) { rv[t] = ov2; ri[t] = oi2; }
                }
                __syncthreads();
            }
            if (t == 0) {
                out[b * KK + round] = rv[0];
                s_top[round] = ri[0];
            }
            int wi = ri[0];
#pragma unroll
            for (int j = 0; j < KK; ++j) {
                if (ix[j] == wi) { v[j] = -CUDART_INF_F; ix[j] = INT_MAX; }
            }
            __syncthreads();
        }
    }
    __syncthreads();

    // ---- inline gather: 16 rows x 512 f32 = 2048 float4, 8 per thread ----
    float* gout = out + (size_t)BB * KK + (size_t)b * KK * DD;
#pragma unroll
    for (int i = 0; i < 8; ++i) {
        int e = t + i * 256;           // 0..2047 float4 slots
        int j = e >> 7;                // row 0..15
        int c = e & 127;               // float4 col
        const float4* src = (const float4*)(M + (size_t)s_top[j] * DD);
        ((float4*)(gout + (size_t)j * DD))[c] = src[c];
    }
}

// ---------------------------------------------------------------------------
extern "C" void kernel_launch(void* const* d_in, const int* in_sizes, int n_in,
                              void* d_out, int out_size) {
    const float* Q   = (const float*)d_in[0];
    const float* M   = (const float*)d_in[1];
    const float* imp = (const float*)d_in[2];
    float* out = (float*)d_out;

    prep_kernel<<<MBLKS + BB / 8, 256>>>(Q, M, imp);

    dim3 ggrid(BB / BM, NN / BN);   // (8, 1024)
    gemm_scan_kernel<<<ggrid, 64, GEMM_SMEM>>>();

    finalize_kernel<<<BB, 256>>>(Q, M, imp, out);
}

// round 13
// speedup vs baseline: 1.0747x; 1.0747x over previous
#include <cuda_runtime.h>
#include <cuda_bf16.h>
#include <math_constants.h>
#include <climits>
#include <cstdint>

#define BB 512
#define NN 131072
#define DD 512
#define KK 16

#define CAND_CAP 2048
#define SEL_CAP  128
#define THRESH   0.14f
#define EPS_SCR  3e-3f   // >> bf16 screen error (~1.5e-4)
#define SEL_GAP  6e-3f   // screen-value cut below v16_screen

// ---------------------------------------------------------------------------
__device__ __nv_bfloat16  g_mbf[(size_t)NN * DD];
__device__ __nv_bfloat16  g_qbf[(size_t)BB * DD];
__device__ float g_qrs[BB];
__device__ float g_nb[NN];
__device__ int   g_cand[(size_t)BB * CAND_CAP];
__device__ float g_candval[(size_t)BB * CAND_CAP];
__device__ int   g_candcnt[BB];

__device__ __forceinline__ uint32_t smem_u32(const void* p) {
    uint32_t a;
    asm("{ .reg .u64 t; cvta.to.shared.u64 t, %1; cvt.u32.u64 %0, t; }" : "=r"(a) : "l"(p));
    return a;
}
__device__ __forceinline__ void ldmatrix_x4(uint32_t& r0, uint32_t& r1, uint32_t& r2, uint32_t& r3,
                                            uint32_t addr) {
    asm volatile("ldmatrix.sync.aligned.m8n8.x4.shared.b16 {%0,%1,%2,%3}, [%4];"
                 : "=r"(r0), "=r"(r1), "=r"(r2), "=r"(r3) : "r"(addr));
}
__device__ __forceinline__ void mma_bf16(float* c, const uint32_t* a, const uint32_t* b) {
    asm volatile(
        "mma.sync.aligned.m16n8k16.row.col.f32.bf16.bf16.f32 "
        "{%0,%1,%2,%3}, {%4,%5,%6,%7}, {%8,%9}, {%0,%1,%2,%3};"
        : "+f"(c[0]), "+f"(c[1]), "+f"(c[2]), "+f"(c[3])
        : "r"(a[0]), "r"(a[1]), "r"(a[2]), "r"(a[3]), "r"(b[0]), "r"(b[1]));
}
__device__ __forceinline__ void cp_async16(uint32_t smem_addr, const void* gptr) {
    asm volatile("cp.async.cg.shared.global [%0], [%1], 16;" :: "r"(smem_addr), "l"(gptr));
}
__device__ __forceinline__ void cp_commit() {
    asm volatile("cp.async.commit_group;" ::: "memory");
}
template <int N>
__device__ __forceinline__ void cp_wait() {
    asm volatile("cp.async.wait_group %0;" :: "n"(N) : "memory");
}

// ---------------------------------------------------------------------------
// Merged prep: zero counters (block 0) + bf16 conversion + scales for M and Q.
// ---------------------------------------------------------------------------
#define MBLKS (NN / 8)

__global__ void prep_kernel(const float* __restrict__ Q, const float* __restrict__ M,
                            const float* __restrict__ imp) {
    if (blockIdx.x == 0) {
        int t = threadIdx.x;
#pragma unroll
        for (int i = 0; i < BB / 256; ++i) g_candcnt[t + i * 256] = 0;
    }
    const int wrow = blockIdx.x * 8 + (threadIdx.x >> 5);
    const int lane = threadIdx.x & 31;

    const float* src;
    __nv_bfloat16* dst;
    int row;
    bool is_m;
    if (blockIdx.x < MBLKS) {
        row = wrow; is_m = true;
        if (row >= NN) return;
        src = M + (size_t)row * DD;
        dst = g_mbf + (size_t)row * DD;
    } else {
        row = wrow - NN; is_m = false;
        if (row >= BB) return;
        src = Q + (size_t)row * DD;
        dst = g_qbf + (size_t)row * DD;
    }

    const float4* s4 = (const float4*)src;
    float s = 0.0f;
#pragma unroll
    for (int i = 0; i < 4; ++i) {
        float4 f = s4[i * 32 + lane];
        s += f.x * f.x + f.y * f.y + f.z * f.z + f.w * f.w;
        __nv_bfloat162 p0 = __floats2bfloat162_rn(f.x, f.y);
        __nv_bfloat162 p1 = __floats2bfloat162_rn(f.z, f.w);
        uint2 u;
        u.x = *(uint32_t*)&p0;
        u.y = *(uint32_t*)&p1;
        *(uint2*)(dst + (size_t)(i * 32 + lane) * 4) = u;
    }
#pragma unroll
    for (int o = 16; o > 0; o >>= 1) s += __shfl_xor_sync(0xffffffffu, s, o);
    if (lane == 0) {
        float nrm = sqrtf(s);
        if (is_m) g_nb[row] = (1.0f + 0.3f * imp[row]) / nrm;
        else      g_qrs[row] = 1.0f / nrm;
    }
}

// ---------------------------------------------------------------------------
// bf16 HMMA GEMM (NT) + fused threshold-scan epilogue.
// R9/R11 geometry (measured 287us twice): 128x128 CTA, 4 warps 2x2,
// warp 64x64, KBLK=64, 3-stage cp.async, one barrier per kt, 2 CTAs/SM.
// ---------------------------------------------------------------------------
#define BM 128
#define BN 128
#define KBLK 64
#define NKB  (DD / KBLK)   // 8
#define APAD 72
#define STAGES 3
#define ASTG (BM * APAD * 2)
#define BSTG (BN * APAD * 2)
#define GEMM_SMEM (STAGES * (ASTG + BSTG))   // 110592 B

__device__ __forceinline__ void issue_stage(uint32_t sA, uint32_t sB,
                                            const __nv_bfloat16* Abase,
                                            const __nv_bfloat16* Bbase,
                                            int kb, int stage, int tid) {
    const uint32_t a0 = sA + (uint32_t)stage * ASTG;
    const uint32_t b0 = sB + (uint32_t)stage * BSTG;
    const int koff = kb * KBLK;
#pragma unroll
    for (int i = 0; i < 8; ++i) {
        int idx = tid + i * 128;
        int r = idx >> 3, c = idx & 7;
        cp_async16(a0 + (uint32_t)(r * APAD + c * 8) * 2,
                   Abase + (size_t)r * DD + koff + c * 8);
    }
#pragma unroll
    for (int i = 0; i < 8; ++i) {
        int idx = tid + i * 128;
        int r = idx >> 3, c = idx & 7;
        cp_async16(b0 + (uint32_t)(r * APAD + c * 8) * 2,
                   Bbase + (size_t)r * DD + koff + c * 8);
    }
    cp_commit();
}

__global__ __launch_bounds__(128, 2)
void gemm_scan_kernel() {
    extern __shared__ __align__(16) char smem[];
    const uint32_t sA = smem_u32(smem);
    const uint32_t sB = sA + STAGES * ASTG;

    const int tid  = threadIdx.x;
    const int warp = tid >> 5;
    const int lane = tid & 31;
    const int wm = warp & 1;
    const int wn = warp >> 1;

    const int b0 = blockIdx.x * BM;
    const int n0 = blockIdx.y * BN;

    const __nv_bfloat16* Abase = g_qbf + (size_t)b0 * DD;
    const __nv_bfloat16* Bbase = g_mbf + (size_t)n0 * DD;

    float acc[4][8][4];
#pragma unroll
    for (int mt = 0; mt < 4; ++mt)
#pragma unroll
        for (int nt = 0; nt < 8; ++nt)
#pragma unroll
            for (int r = 0; r < 4; ++r) acc[mt][nt][r] = 0.0f;

#pragma unroll
    for (int s = 0; s < STAGES - 1; ++s)
        issue_stage(sA, sB, Abase, Bbase, s, s, tid);

    const int rbase = lane & 15;
    const int colhalf = (lane >> 4) * 8;

    for (int kt = 0; kt < NKB; ++kt) {
        if (kt == NKB - 1) cp_wait<0>();
        else               cp_wait<1>();
        __syncthreads();

        if (kt + STAGES - 1 < NKB)
            issue_stage(sA, sB, Abase, Bbase, kt + STAGES - 1,
                        (kt + STAGES - 1) % STAGES, tid);

        const int cur = kt % STAGES;
        const uint32_t aST = sA + (uint32_t)cur * ASTG;
        const uint32_t bST = sB + (uint32_t)cur * BSTG;

#pragma unroll
        for (int ks = 0; ks < KBLK / 16; ++ks) {
            const int col = ks * 16 + colhalf;
            uint32_t af[4][4];
#pragma unroll
            for (int mt = 0; mt < 4; ++mt) {
                int row = wm * 64 + mt * 16 + rbase;
                ldmatrix_x4(af[mt][0], af[mt][1], af[mt][2], af[mt][3],
                            aST + (uint32_t)(row * APAD + col) * 2);
            }
            uint32_t bf[8][2];
#pragma unroll
            for (int ng = 0; ng < 4; ++ng) {
                int row = wn * 64 + ng * 16 + rbase;
                uint32_t r0, r1, r2, r3;
                ldmatrix_x4(r0, r1, r2, r3, bST + (uint32_t)(row * APAD + col) * 2);
                bf[ng * 2 + 0][0] = r0; bf[ng * 2 + 0][1] = r2;
                bf[ng * 2 + 1][0] = r1; bf[ng * 2 + 1][1] = r3;
            }
#pragma unroll
            for (int mt = 0; mt < 4; ++mt)
#pragma unroll
                for (int nt = 0; nt < 8; ++nt)
                    mma_bf16(acc[mt][nt], af[mt], bf[nt]);
        }
    }

    // Epilogue: threshold scan, push (index, screen value)
    const int r0 = lane >> 2;
    const int c0 = (lane & 3) * 2;
#pragma unroll
    for (int mt = 0; mt < 4; ++mt) {
        const int brow0 = b0 + wm * 64 + mt * 16 + r0;
        const float q0 = g_qrs[brow0];
        const float q1 = g_qrs[brow0 + 8];
#pragma unroll
        for (int nt = 0; nt < 8; ++nt) {
            const int n = n0 + wn * 64 + nt * 8 + c0;
            const float nb0 = g_nb[n];
            const float nb1 = g_nb[n + 1];
            float v00 = acc[mt][nt][0] * q0 * nb0;
            float v01 = acc[mt][nt][1] * q0 * nb1;
            float v10 = acc[mt][nt][2] * q1 * nb0;
            float v11 = acc[mt][nt][3] * q1 * nb1;
            if (v00 > THRESH) {
                int s = atomicAdd(&g_candcnt[brow0], 1);
                if (s < CAND_CAP) {
                    g_cand[(size_t)brow0 * CAND_CAP + s] = n;
                    g_candval[(size_t)brow0 * CAND_CAP + s] = v00;
                }
            }
            if (v01 > THRESH) {
                int s = atomicAdd(&g_candcnt[brow0], 1);
                if (s < CAND_CAP) {
                    g_cand[(size_t)brow0 * CAND_CAP + s] = n + 1;
                    g_candval[(size_t)brow0 * CAND_CAP + s] = v01;
                }
            }
            if (v10 > THRESH) {
                int s = atomicAdd(&g_candcnt[brow0 + 8], 1);
                if (s < CAND_CAP) {
                    g_cand[(size_t)(brow0 + 8) * CAND_CAP + s] = n;
                    g_candval[(size_t)(brow0 + 8) * CAND_CAP + s] = v10;
                }
            }
            if (v11 > THRESH) {
                int s = atomicAdd(&g_candcnt[brow0 + 8], 1);
                if (s < CAND_CAP) {
                    g_cand[(size_t)(brow0 + 8) * CAND_CAP + s] = n + 1;
                    g_candval[(size_t)(brow0 + 8) * CAND_CAP + s] = v11;
                }
            }
        }
    }
}

// ---------------------------------------------------------------------------
// Finalize: screen-value preselection + exact f32 rescore + certification
// + inline brute-force fallback (flagged only) + inline gather. One launch.
// ---------------------------------------------------------------------------
__global__ void finalize_kernel(const float* __restrict__ Q, const float* __restrict__ M,
                                const float* __restrict__ imp, float* __restrict__ out) {
    const int b = blockIdx.x;
    const int t = threadIdx.x;
    const int w = t >> 5;
    const int lane = t & 31;
    const int raw = g_candcnt[b];
    const int cnt = min(raw, CAND_CAP);

    __shared__ float s_val[CAND_CAP];
    __shared__ int   s_idx[CAND_CAP];
    __shared__ float s_q[DD];
    __shared__ float rv[256];
    __shared__ int   ri[256];
    __shared__ int   s_seln[SEL_CAP];
    __shared__ float s_excl[256];
    __shared__ float e_val[SEL_CAP];
    __shared__ int   e_n[SEL_CAP];
    __shared__ int   s_selcnt;
    __shared__ float s_v16s;
    __shared__ int   s_bad;
    __shared__ int   s_top[KK];

    for (int d = t; d < DD; d += 256) s_q[d] = Q[(size_t)b * DD + d];
    for (int s = t; s < cnt; s += 256) {
        s_val[s] = g_candval[(size_t)b * CAND_CAP + s];
        s_idx[s] = g_cand[(size_t)b * CAND_CAP + s];
    }
    if (t == 0) s_selcnt = 0;
    __syncthreads();

    // qn once (per warp redundant)
    float q2 = 0.0f;
    for (int d = lane; d < DD; d += 32) { float x = s_q[d]; q2 = fmaf(x, x, q2); }
#pragma unroll
    for (int o = 16; o > 0; o >>= 1) q2 += __shfl_xor_sync(0xffffffffu, q2, o);
    const float qn = sqrtf(q2);

    // ---- exact 16th-largest screen value ----
    float lv[KK]; int ls[KK];
#pragma unroll
    for (int i = 0; i < KK; ++i) { lv[i] = -CUDART_INF_F; ls[i] = INT_MAX; }
    for (int s = t; s < cnt; s += 256) {
        float x = s_val[s];
        if (x > lv[KK - 1]) {
            lv[KK - 1] = x; ls[KK - 1] = s;
#pragma unroll
            for (int p = KK - 1; p >= 1; --p) {
                if (lv[p] > lv[p - 1]) {
                    float tv = lv[p]; lv[p] = lv[p - 1]; lv[p - 1] = tv;
                    int   ti = ls[p]; ls[p] = ls[p - 1]; ls[p - 1] = ti;
                }
            }
        }
    }
    for (int round = 0; round < KK; ++round) {
        float bvv = -CUDART_INF_F; int bss = INT_MAX;
#pragma unroll
        for (int j = 0; j < KK; ++j) {
            if (lv[j] > bvv || (lv[j] == bvv && ls[j] < bss)) { bvv = lv[j]; bss = ls[j]; }
        }
        rv[t] = bvv; ri[t] = bss;
        __syncthreads();
        for (int s = 128; s > 0; s >>= 1) {
            if (t < s) {
                float ov = rv[t + s]; int os = ri[t + s];
                if (ov > rv[t] || (ov == rv[t] && os < ri[t])) { rv[t] = ov; ri[t] = os; }
            }
            __syncthreads();
        }
        if (round == KK - 1) {
            if (t == 0) s_v16s = rv[0];
        }
        int wslot = ri[0];
#pragma unroll
        for (int j = 0; j < KK; ++j) {
            if (ls[j] == wslot) { lv[j] = -CUDART_INF_F; ls[j] = INT_MAX; }
        }
        __syncthreads();
    }
    const float thresh2 = s_v16s - SEL_GAP;

    // ---- select survivors; track max excluded screen value ----
    float exl = -CUDART_INF_F;
    for (int s = t; s < cnt; s += 256) {
        if (s_val[s] >= thresh2) {
            int pos = atomicAdd(&s_selcnt, 1);
            if (pos < SEL_CAP) s_seln[pos] = s_idx[s];
        } else {
            exl = fmaxf(exl, s_val[s]);
        }
    }
    s_excl[t] = exl;
    __syncthreads();
    for (int s = 128; s > 0; s >>= 1) {
        if (t < s) s_excl[t] = fmaxf(s_excl[t], s_excl[t + s]);
        __syncthreads();
    }
    const float excl_max = s_excl[0];
    const int selraw = s_selcnt;
    const int nsel = min(selraw, SEL_CAP);

    // ---- exact f32 rescore of survivors (warp per candidate) ----
    for (int s = w; s < nsel; s += 8) {
        const int idx = s_seln[s];
        const float4* m = (const float4*)(M + (size_t)idx * DD);
        float dot = 0.0f, m2 = 0.0f;
#pragma unroll
        for (int i = 0; i < 4; ++i) {
            float4 mv = m[i * 32 + lane];
            const float* qp = &s_q[(i * 32 + lane) * 4];
            dot = fmaf(mv.x, qp[0], dot); dot = fmaf(mv.y, qp[1], dot);
            dot = fmaf(mv.z, qp[2], dot); dot = fmaf(mv.w, qp[3], dot);
            m2  = fmaf(mv.x, mv.x, m2);   m2  = fmaf(mv.y, mv.y, m2);
            m2  = fmaf(mv.z, mv.z, m2);   m2  = fmaf(mv.w, mv.w, m2);
        }
#pragma unroll
        for (int o = 16; o > 0; o >>= 1) {
            dot += __shfl_xor_sync(0xffffffffu, dot, o);
            m2  += __shfl_xor_sync(0xffffffffu, m2, o);
        }
        if (lane == 0) {
            float den = fmaxf(qn * sqrtf(m2), 1e-8f);
            e_val[s] = (dot / den) * (1.0f + 0.3f * imp[idx]);
            e_n[s] = idx;
        }
    }
    __syncthreads();

    if (t == 0) {
        float bv[KK]; int bi[KK];
#pragma unroll
        for (int i = 0; i < KK; ++i) { bv[i] = -CUDART_INF_F; bi[i] = INT_MAX; }
        for (int s = 0; s < nsel; ++s) {
            float val = e_val[s]; int id = e_n[s];
            if (val > bv[KK - 1] || (val == bv[KK - 1] && id < bi[KK - 1])) {
                bv[KK - 1] = val; bi[KK - 1] = id;
                for (int p = KK - 1; p >= 1; --p) {
                    bool sw = (bv[p] > bv[p - 1]) || (bv[p] == bv[p - 1] && bi[p] < bi[p - 1]);
                    if (!sw) break;
                    float tv = bv[p]; bv[p] = bv[p - 1]; bv[p - 1] = tv;
                    int   ti = bi[p]; bi[p] = bi[p - 1]; bi[p - 1] = ti;
                }
            }
        }
        bool bad = (raw < KK) || (raw > CAND_CAP) || (selraw > SEL_CAP) || (nsel < KK) ||
                   (bv[KK - 1] < THRESH + EPS_SCR) ||
                   (cnt > nsel && bv[KK - 1] < excl_max + EPS_SCR);
        s_bad = bad ? 1 : 0;
        for (int r = 0; r < KK; ++r) {
            out[b * KK + r] = bv[r];
            s_top[r] = bi[r];
        }
    }
    __syncthreads();

    // ---- brute-force fallback (only if certification failed) ----
    if (s_bad) {
        float v[KK]; int ix[KK];
#pragma unroll
        for (int i = 0; i < KK; ++i) { v[i] = -CUDART_INF_F; ix[i] = INT_MAX; }
        for (int n = t; n < NN; n += 256) {
            const float* m = M + (size_t)n * DD;
            float dot = 0.0f, m2 = 0.0f;
            for (int d = 0; d < DD; ++d) {
                float a = s_q[d], bb = m[d];
                dot = fmaf(a, bb, dot); m2 = fmaf(bb, bb, m2);
            }
            float den = fmaxf(qn * sqrtf(m2), 1e-8f);
            float val = (dot / den) * (1.0f + 0.3f * imp[n]);
            if (val > v[KK - 1]) {
                v[KK - 1] = val; ix[KK - 1] = n;
                for (int p = KK - 1; p >= 1; --p) {
                    if (v[p] > v[p - 1]) {
                        float tv = v[p]; v[p] = v[p - 1]; v[p - 1] = tv;
                        int ti = ix[p]; ix[p] = ix[p - 1]; ix[p - 1] = ti;
                    }
                }
            }
        }
        for (int round = 0; round < KK; ++round) {
            float bvv = -CUDART_INF_F; int bii = INT_MAX;
#pragma unroll
            for (int j = 0; j < KK; ++j) {
                bool better = (v[j] > bvv) || (v[j] == bvv && ix[j] < bii);
                if (better) { bvv = v[j]; bii = ix[j]; }
            }
            rv[t] = bvv; ri[t] = bii;
            __syncthreads();
            for (int s = 128; s > 0; s >>= 1) {
                if (t < s) {
                    float ov2 = rv[t + s]; int oi2 = ri[t + s];
                    if (ov2 > rv[t] || (ov2 == rv[t] && oi2 < ri[t])) { rv[t] = ov2; ri[t] = oi2; }
                }
                __syncthreads();
            }
            if (t == 0) {
                out[b * KK + round] = rv[0];
                s_top[round] = ri[0];
            }
            int wi = ri[0];
#pragma unroll
            for (int j = 0; j < KK; ++j) {
                if (ix[j] == wi) { v[j] = -CUDART_INF_F; ix[j] = INT_MAX; }
            }
            __syncthreads();
        }
    }
    __syncthreads();

    // ---- inline gather: 16 rows x 512 f32 = 2048 float4, 8 per thread ----
    float* gout = out + (size_t)BB * KK + (size_t)b * KK * DD;
#pragma unroll
    for (int i = 0; i < 8; ++i) {
        int e = t + i * 256;           // 0..2047 float4 slots
        int j = e >> 7;                // row 0..15
        int c = e & 127;               // float4 col
        const float4* src = (const float4*)(M + (size_t)s_top[j] * DD);
        ((float4*)(gout + (size_t)j * DD))[c] = src[c];
    }
}

// ---------------------------------------------------------------------------
extern "C" void kernel_launch(void* const* d_in, const int* in_sizes, int n_in,
                              void* d_out, int out_size) {
    const float* Q   = (const float*)d_in[0];
    const float* M   = (const float*)d_in[1];
    const float* imp = (const float*)d_in[2];
    float* out = (float*)d_out;

    cudaFuncSetAttribute(gemm_scan_kernel, cudaFuncAttributeMaxDynamicSharedMemorySize, GEMM_SMEM);

    prep_kernel<<<MBLKS + BB / 8, 256>>>(Q, M, imp);

    dim3 ggrid(BB / BM, NN / BN);   // (4, 1024)
    gemm_scan_kernel<<<ggrid, 128, GEMM_SMEM>>>();

    finalize_kernel<<<BB, 256>>>(Q, M, imp, out);
}

// round 14
// speedup vs baseline: 1.2038x; 1.1201x over previous
#include <cuda_runtime.h>
#include <cuda_bf16.h>
#include <math_constants.h>
#include <climits>
#include <cstdint>

#define BB 512
#define NN 131072
#define DD 512
#define KK 16

#define CAND_CAP 2048
#define SEL_CAP  128
#define THRESH   0.14f
#define EPS_SCR  3e-3f   // >> bf16 screen error (~1.5e-4)
#define SEL_GAP  6e-3f   // screen-value cut below v16_screen

// ---------------------------------------------------------------------------
__device__ __nv_bfloat16  g_mbf[(size_t)NN * DD];
__device__ __nv_bfloat16  g_qbf[(size_t)BB * DD];
__device__ float g_qrs[BB];
__device__ float g_nb[NN];
__device__ int   g_cand[(size_t)BB * CAND_CAP];
__device__ float g_candval[(size_t)BB * CAND_CAP];
__device__ int   g_candcnt[BB];
__device__ int   g_flag[BB];

__device__ __forceinline__ uint32_t smem_u32(const void* p) {
    uint32_t a;
    asm("{ .reg .u64 t; cvta.to.shared.u64 t, %1; cvt.u32.u64 %0, t; }" : "=r"(a) : "l"(p));
    return a;
}
__device__ __forceinline__ void ldmatrix_x4(uint32_t& r0, uint32_t& r1, uint32_t& r2, uint32_t& r3,
                                            uint32_t addr) {
    asm volatile("ldmatrix.sync.aligned.m8n8.x4.shared.b16 {%0,%1,%2,%3}, [%4];"
                 : "=r"(r0), "=r"(r1), "=r"(r2), "=r"(r3) : "r"(addr));
}
__device__ __forceinline__ void mma_bf16(float* c, const uint32_t* a, const uint32_t* b) {
    asm volatile(
        "mma.sync.aligned.m16n8k16.row.col.f32.bf16.bf16.f32 "
        "{%0,%1,%2,%3}, {%4,%5,%6,%7}, {%8,%9}, {%0,%1,%2,%3};"
        : "+f"(c[0]), "+f"(c[1]), "+f"(c[2]), "+f"(c[3])
        : "r"(a[0]), "r"(a[1]), "r"(a[2]), "r"(a[3]), "r"(b[0]), "r"(b[1]));
}
__device__ __forceinline__ void cp_async16(uint32_t smem_addr, const void* gptr) {
    asm volatile("cp.async.cg.shared.global [%0], [%1], 16;" :: "r"(smem_addr), "l"(gptr));
}
__device__ __forceinline__ void cp_commit() {
    asm volatile("cp.async.commit_group;" ::: "memory");
}
template <int N>
__device__ __forceinline__ void cp_wait() {
    asm volatile("cp.async.wait_group %0;" :: "n"(N) : "memory");
}

// ---------------------------------------------------------------------------
// Merged prep: zero counters (block 0) + bf16 conversion + scales for M and Q.
// ---------------------------------------------------------------------------
#define MBLKS (NN / 8)

__global__ void prep_kernel(const float* __restrict__ Q, const float* __restrict__ M,
                            const float* __restrict__ imp) {
    if (blockIdx.x == 0) {
        int t = threadIdx.x;
#pragma unroll
        for (int i = 0; i < BB / 256; ++i) {
            g_candcnt[t + i * 256] = 0;
            g_flag[t + i * 256] = 0;
        }
    }
    const int wrow = blockIdx.x * 8 + (threadIdx.x >> 5);
    const int lane = threadIdx.x & 31;

    const float* src;
    __nv_bfloat16* dst;
    int row;
    bool is_m;
    if (blockIdx.x < MBLKS) {
        row = wrow; is_m = true;
        if (row >= NN) return;
        src = M + (size_t)row * DD;
        dst = g_mbf + (size_t)row * DD;
    } else {
        row = wrow - NN; is_m = false;
        if (row >= BB) return;
        src = Q + (size_t)row * DD;
        dst = g_qbf + (size_t)row * DD;
    }

    const float4* s4 = (const float4*)src;
    float s = 0.0f;
#pragma unroll
    for (int i = 0; i < 4; ++i) {
        float4 f = s4[i * 32 + lane];
        s += f.x * f.x + f.y * f.y + f.z * f.z + f.w * f.w;
        __nv_bfloat162 p0 = __floats2bfloat162_rn(f.x, f.y);
        __nv_bfloat162 p1 = __floats2bfloat162_rn(f.z, f.w);
        uint2 u;
        u.x = *(uint32_t*)&p0;
        u.y = *(uint32_t*)&p1;
        *(uint2*)(dst + (size_t)(i * 32 + lane) * 4) = u;
    }
#pragma unroll
    for (int o = 16; o > 0; o >>= 1) s += __shfl_xor_sync(0xffffffffu, s, o);
    if (lane == 0) {
        float nrm = sqrtf(s);
        if (is_m) g_nb[row] = (1.0f + 0.3f * imp[row]) / nrm;
        else      g_qrs[row] = 1.0f / nrm;
    }
}

// ---------------------------------------------------------------------------
// bf16 HMMA GEMM (NT) + fused threshold-scan epilogue. R9/R11 config.
// ---------------------------------------------------------------------------
#define BM 128
#define BN 128
#define KBLK 64
#define NKB  (DD / KBLK)   // 8
#define APAD 72
#define STAGES 3
#define ASTG (BM * APAD * 2)
#define BSTG (BN * APAD * 2)
#define GEMM_SMEM (STAGES * (ASTG + BSTG))   // 110592 B

__device__ __forceinline__ void issue_stage(uint32_t sA, uint32_t sB,
                                            const __nv_bfloat16* Abase,
                                            const __nv_bfloat16* Bbase,
                                            int kb, int stage, int tid) {
    const uint32_t a0 = sA + (uint32_t)stage * ASTG;
    const uint32_t b0 = sB + (uint32_t)stage * BSTG;
    const int koff = kb * KBLK;
#pragma unroll
    for (int i = 0; i < 8; ++i) {
        int idx = tid + i * 128;
        int r = idx >> 3, c = idx & 7;
        cp_async16(a0 + (uint32_t)(r * APAD + c * 8) * 2,
                   Abase + (size_t)r * DD + koff + c * 8);
    }
#pragma unroll
    for (int i = 0; i < 8; ++i) {
        int idx = tid + i * 128;
        int r = idx >> 3, c = idx & 7;
        cp_async16(b0 + (uint32_t)(r * APAD + c * 8) * 2,
                   Bbase + (size_t)r * DD + koff + c * 8);
    }
    cp_commit();
}

__global__ __launch_bounds__(128, 2)
void gemm_scan_kernel() {
    extern __shared__ __align__(16) char smem[];
    const uint32_t sA = smem_u32(smem);
    const uint32_t sB = sA + STAGES * ASTG;

    const int tid  = threadIdx.x;
    const int warp = tid >> 5;
    const int lane = tid & 31;
    const int wm = warp & 1;
    const int wn = warp >> 1;

    const int b0 = blockIdx.x * BM;
    const int n0 = blockIdx.y * BN;

    const __nv_bfloat16* Abase = g_qbf + (size_t)b0 * DD;
    const __nv_bfloat16* Bbase = g_mbf + (size_t)n0 * DD;

    float acc[4][8][4];
#pragma unroll
    for (int mt = 0; mt < 4; ++mt)
#pragma unroll
        for (int nt = 0; nt < 8; ++nt)
#pragma unroll
            for (int r = 0; r < 4; ++r) acc[mt][nt][r] = 0.0f;

#pragma unroll
    for (int s = 0; s < STAGES - 1; ++s)
        issue_stage(sA, sB, Abase, Bbase, s, s, tid);

    const int rbase = lane & 15;
    const int colhalf = (lane >> 4) * 8;

    for (int kt = 0; kt < NKB; ++kt) {
        if (kt == NKB - 1) cp_wait<0>();
        else               cp_wait<1>();
        __syncthreads();

        if (kt + STAGES - 1 < NKB)
            issue_stage(sA, sB, Abase, Bbase, kt + STAGES - 1,
                        (kt + STAGES - 1) % STAGES, tid);

        const int cur = kt % STAGES;
        const uint32_t aST = sA + (uint32_t)cur * ASTG;
        const uint32_t bST = sB + (uint32_t)cur * BSTG;

#pragma unroll
        for (int ks = 0; ks < KBLK / 16; ++ks) {
            const int col = ks * 16 + colhalf;
            uint32_t af[4][4];
#pragma unroll
            for (int mt = 0; mt < 4; ++mt) {
                int row = wm * 64 + mt * 16 + rbase;
                ldmatrix_x4(af[mt][0], af[mt][1], af[mt][2], af[mt][3],
                            aST + (uint32_t)(row * APAD + col) * 2);
            }
            uint32_t bf[8][2];
#pragma unroll
            for (int ng = 0; ng < 4; ++ng) {
                int row = wn * 64 + ng * 16 + rbase;
                uint32_t r0, r1, r2, r3;
                ldmatrix_x4(r0, r1, r2, r3, bST + (uint32_t)(row * APAD + col) * 2);
                bf[ng * 2 + 0][0] = r0; bf[ng * 2 + 0][1] = r2;
                bf[ng * 2 + 1][0] = r1; bf[ng * 2 + 1][1] = r3;
            }
#pragma unroll
            for (int mt = 0; mt < 4; ++mt)
#pragma unroll
                for (int nt = 0; nt < 8; ++nt)
                    mma_bf16(acc[mt][nt], af[mt], bf[nt]);
        }
    }

    const int r0 = lane >> 2;
    const int c0 = (lane & 3) * 2;
#pragma unroll
    for (int mt = 0; mt < 4; ++mt) {
        const int brow0 = b0 + wm * 64 + mt * 16 + r0;
        const float q0 = g_qrs[brow0];
        const float q1 = g_qrs[brow0 + 8];
#pragma unroll
        for (int nt = 0; nt < 8; ++nt) {
            const int n = n0 + wn * 64 + nt * 8 + c0;
            const float nb0 = g_nb[n];
            const float nb1 = g_nb[n + 1];
            float v00 = acc[mt][nt][0] * q0 * nb0;
            float v01 = acc[mt][nt][1] * q0 * nb1;
            float v10 = acc[mt][nt][2] * q1 * nb0;
            float v11 = acc[mt][nt][3] * q1 * nb1;
            if (v00 > THRESH) {
                int s = atomicAdd(&g_candcnt[brow0], 1);
                if (s < CAND_CAP) {
                    g_cand[(size_t)brow0 * CAND_CAP + s] = n;
                    g_candval[(size_t)brow0 * CAND_CAP + s] = v00;
                }
            }
            if (v01 > THRESH) {
                int s = atomicAdd(&g_candcnt[brow0], 1);
                if (s < CAND_CAP) {
                    g_cand[(size_t)brow0 * CAND_CAP + s] = n + 1;
                    g_candval[(size_t)brow0 * CAND_CAP + s] = v01;
                }
            }
            if (v10 > THRESH) {
                int s = atomicAdd(&g_candcnt[brow0 + 8], 1);
                if (s < CAND_CAP) {
                    g_cand[(size_t)(brow0 + 8) * CAND_CAP + s] = n;
                    g_candval[(size_t)(brow0 + 8) * CAND_CAP + s] = v10;
                }
            }
            if (v11 > THRESH) {
                int s = atomicAdd(&g_candcnt[brow0 + 8], 1);
                if (s < CAND_CAP) {
                    g_cand[(size_t)(brow0 + 8) * CAND_CAP + s] = n + 1;
                    g_candval[(size_t)(brow0 + 8) * CAND_CAP + s] = v11;
                }
            }
        }
    }
}

// ---------------------------------------------------------------------------
// Rescore: hierarchical 16th-screen-value selection (warp shuffles + serial
// merge -> ~2 barriers instead of ~128), exact f32 rescore of survivors,
// certification, and inline gather for certified queries.
// ---------------------------------------------------------------------------
__global__ void rescore_kernel(const float* __restrict__ Q, const float* __restrict__ M,
                               const float* __restrict__ imp, float* __restrict__ out) {
    const int b = blockIdx.x;
    const int t = threadIdx.x;
    const int w = t >> 5;
    const int lane = t & 31;
    const int raw = g_candcnt[b];
    const int cnt = min(raw, CAND_CAP);

    __shared__ float s_val[CAND_CAP];
    __shared__ int   s_idx[CAND_CAP];
    __shared__ float s_q[DD];
    __shared__ float s_wtop[8][KK];
    __shared__ int   s_seln[SEL_CAP];
    __shared__ float s_excl[256];
    __shared__ float e_val[SEL_CAP];
    __shared__ int   e_n[SEL_CAP];
    __shared__ int   s_selcnt;
    __shared__ float s_v16s;
    __shared__ int   s_bad;
    __shared__ int   s_top[KK];

    for (int d = t; d < DD; d += 256) s_q[d] = Q[(size_t)b * DD + d];
    for (int s = t; s < cnt; s += 256) {
        s_val[s] = g_candval[(size_t)b * CAND_CAP + s];
        s_idx[s] = g_cand[(size_t)b * CAND_CAP + s];
    }
    if (t == 0) s_selcnt = 0;
    __syncthreads();

    // qn (per warp redundant)
    float q2 = 0.0f;
    for (int d = lane; d < DD; d += 32) { float x = s_q[d]; q2 = fmaf(x, x, q2); }
#pragma unroll
    for (int o = 16; o > 0; o >>= 1) q2 += __shfl_xor_sync(0xffffffffu, q2, o);
    const float qn = sqrtf(q2);

    // ---- per-thread sorted top-16 of screen values (<=8 elems/thread) ----
    float lv[KK];
#pragma unroll
    for (int i = 0; i < KK; ++i) lv[i] = -CUDART_INF_F;
    for (int s = t; s < cnt; s += 256) {
        float x = s_val[s];
        if (x > lv[KK - 1]) {
            lv[KK - 1] = x;
#pragma unroll
            for (int p = KK - 1; p >= 1; --p) {
                if (lv[p] > lv[p - 1]) { float tv = lv[p]; lv[p] = lv[p - 1]; lv[p - 1] = tv; }
            }
        }
    }

    // ---- warp top-16 via 16 rounds of shuffle argmax (barrier-free) ----
    {
        int h = 0;
#pragma unroll
        for (int r = 0; r < KK; ++r) {
            float cand = (h < KK) ? lv[h] : -CUDART_INF_F;
            float best = cand; int bl = lane;
#pragma unroll
            for (int o = 16; o > 0; o >>= 1) {
                float ov = __shfl_xor_sync(0xffffffffu, best, o);
                int obl = __shfl_xor_sync(0xffffffffu, bl, o);
                if (ov > best || (ov == best && obl < bl)) { best = ov; bl = obl; }
            }
            if (lane == bl) h++;
            if (lane == 0) s_wtop[w][r] = best;
        }
    }
    __syncthreads();

    // ---- 8-way merge of sorted warp lists -> exact global 16th ----
    if (t == 0) {
        int heads[8] = {0, 0, 0, 0, 0, 0, 0, 0};
        float v16 = -CUDART_INF_F;
        for (int r = 0; r < KK; ++r) {
            float best = -CUDART_INF_F; int bw = 0;
#pragma unroll
            for (int wq = 0; wq < 8; ++wq) {
                float x = (heads[wq] < KK) ? s_wtop[wq][heads[wq]] : -CUDART_INF_F;
                if (x > best) { best = x; bw = wq; }
            }
            heads[bw]++;
            v16 = best;
        }
        s_v16s = v16;
    }
    __syncthreads();
    const float thresh2 = s_v16s - SEL_GAP;

    // ---- select survivors; track max excluded screen value ----
    float exl = -CUDART_INF_F;
    for (int s = t; s < cnt; s += 256) {
        if (s_val[s] >= thresh2) {
            int pos = atomicAdd(&s_selcnt, 1);
            if (pos < SEL_CAP) s_seln[pos] = s_idx[s];
        } else {
            exl = fmaxf(exl, s_val[s]);
        }
    }
    s_excl[t] = exl;
    __syncthreads();
    for (int s = 128; s > 0; s >>= 1) {
        if (t < s) s_excl[t] = fmaxf(s_excl[t], s_excl[t + s]);
        __syncthreads();
    }
    const float excl_max = s_excl[0];
    const int selraw = s_selcnt;
    const int nsel = min(selraw, SEL_CAP);

    // ---- exact f32 rescore of survivors (warp per candidate) ----
    for (int s = w; s < nsel; s += 8) {
        const int idx = s_seln[s];
        const float4* m = (const float4*)(M + (size_t)idx * DD);
        float dot = 0.0f, m2 = 0.0f;
#pragma unroll
        for (int i = 0; i < 4; ++i) {
            float4 mv = m[i * 32 + lane];
            const float* qp = &s_q[(i * 32 + lane) * 4];
            dot = fmaf(mv.x, qp[0], dot); dot = fmaf(mv.y, qp[1], dot);
            dot = fmaf(mv.z, qp[2], dot); dot = fmaf(mv.w, qp[3], dot);
            m2  = fmaf(mv.x, mv.x, m2);   m2  = fmaf(mv.y, mv.y, m2);
            m2  = fmaf(mv.z, mv.z, m2);   m2  = fmaf(mv.w, mv.w, m2);
        }
#pragma unroll
        for (int o = 16; o > 0; o >>= 1) {
            dot += __shfl_xor_sync(0xffffffffu, dot, o);
            m2  += __shfl_xor_sync(0xffffffffu, m2, o);
        }
        if (lane == 0) {
            float den = fmaxf(qn * sqrtf(m2), 1e-8f);
            e_val[s] = (dot / den) * (1.0f + 0.3f * imp[idx]);
            e_n[s] = idx;
        }
    }
    __syncthreads();

    if (t == 0) {
        float bv[KK]; int bi[KK];
#pragma unroll
        for (int i = 0; i < KK; ++i) { bv[i] = -CUDART_INF_F; bi[i] = INT_MAX; }
        for (int s = 0; s < nsel; ++s) {
            float val = e_val[s]; int id = e_n[s];
            if (val > bv[KK - 1] || (val == bv[KK - 1] && id < bi[KK - 1])) {
                bv[KK - 1] = val; bi[KK - 1] = id;
                for (int p = KK - 1; p >= 1; --p) {
                    bool sw = (bv[p] > bv[p - 1]) || (bv[p] == bv[p - 1] && bi[p] < bi[p - 1]);
                    if (!sw) break;
                    float tv = bv[p]; bv[p] = bv[p - 1]; bv[p - 1] = tv;
                    int   ti = bi[p]; bi[p] = bi[p - 1]; bi[p - 1] = ti;
                }
            }
        }
        bool bad = (raw < KK) || (raw > CAND_CAP) || (selraw > SEL_CAP) || (nsel < KK) ||
                   (bv[KK - 1] < THRESH + EPS_SCR) ||
                   (cnt > nsel && bv[KK - 1] < excl_max + EPS_SCR);
        s_bad = bad ? 1 : 0;
        g_flag[b] = bad ? 1 : 0;
        for (int r = 0; r < KK; ++r) {
            out[b * KK + r] = bv[r];
            s_top[r] = bi[r];
        }
    }
    __syncthreads();

    // ---- inline gather (certified queries; flagged ones redone by fallback) ----
    if (!s_bad) {
        float* gout = out + (size_t)BB * KK + (size_t)b * KK * DD;
#pragma unroll
        for (int i = 0; i < 8; ++i) {
            int e = t + i * 256;
            int j = e >> 7;
            int c = e & 127;
            const float4* src = (const float4*)(M + (size_t)s_top[j] * DD);
            ((float4*)(gout + (size_t)j * DD))[c] = src[c];
        }
    }
}

// ---------------------------------------------------------------------------
// Brute-force exact f32 fallback + gather (flagged queries only).
// ---------------------------------------------------------------------------
__global__ void fallback_kernel(const float* __restrict__ Q, const float* __restrict__ M,
                                const float* __restrict__ imp, float* __restrict__ out) {
    const int b = blockIdx.x;
    if (g_flag[b] == 0) return;
    const int t = threadIdx.x;
    const int lane = t & 31;

    __shared__ float s_q[DD];
    __shared__ int   s_top[KK];
    for (int d = t; d < DD; d += 256) s_q[d] = Q[(size_t)b * DD + d];
    __syncthreads();

    float q2 = 0.0f;
    for (int d = lane; d < DD; d += 32) { float x = s_q[d]; q2 = fmaf(x, x, q2); }
#pragma unroll
    for (int o = 16; o > 0; o >>= 1) q2 += __shfl_xor_sync(0xffffffffu, q2, o);
    const float qn = sqrtf(q2);

    float v[KK]; int ix[KK];
#pragma unroll
    for (int i = 0; i < KK; ++i) { v[i] = -CUDART_INF_F; ix[i] = INT_MAX; }

    for (int n = t; n < NN; n += 256) {
        const float* m = M + (size_t)n * DD;
        float dot = 0.0f, m2 = 0.0f;
        for (int d = 0; d < DD; ++d) {
            float a = s_q[d], bb = m[d];
            dot = fmaf(a, bb, dot); m2 = fmaf(bb, bb, m2);
        }
        float den = fmaxf(qn * sqrtf(m2), 1e-8f);
        float val = (dot / den) * (1.0f + 0.3f * imp[n]);
        if (val > v[KK - 1]) {
            v[KK - 1] = val; ix[KK - 1] = n;
            for (int p = KK - 1; p >= 1; --p) {
                if (v[p] > v[p - 1]) {
                    float tv = v[p]; v[p] = v[p - 1]; v[p - 1] = tv;
                    int ti = ix[p]; ix[p] = ix[p - 1]; ix[p - 1] = ti;
                }
            }
        }
    }

    __shared__ float rv[256];
    __shared__ int   ri[256];
    for (int round = 0; round < KK; ++round) {
        float bvv = -CUDART_INF_F; int bii = INT_MAX;
#pragma unroll
        for (int j = 0; j < KK; ++j) {
            bool better = (v[j] > bvv) || (v[j] == bvv && ix[j] < bii);
            if (better) { bvv = v[j]; bii = ix[j]; }
        }
        rv[t] = bvv; ri[t] = bii;
        __syncthreads();
        for (int s = 128; s > 0; s >>= 1) {
            if (t < s) {
                float ov2 = rv[t + s]; int oi2 = ri[t + s];
                if (ov2 > rv[t] || (ov2 == rv[t] && oi2 < ri[t])) { rv[t] = ov2; ri[t] = oi2; }
            }
            __syncthreads();
        }
        if (t == 0) {
            out[b * KK + round] = rv[0];
            s_top[round] = ri[0];
        }
        int wi = ri[0];
#pragma unroll
        for (int j = 0; j < KK; ++j) {
            if (ix[j] == wi) { v[j] = -CUDART_INF_F; ix[j] = INT_MAX; }
        }
        __syncthreads();
    }

    float* gout = out + (size_t)BB * KK + (size_t)b * KK * DD;
#pragma unroll
    for (int i = 0; i < 8; ++i) {
        int e = t + i * 256;
        int j = e >> 7;
        int c = e & 127;
        const float4* src = (const float4*)(M + (size_t)s_top[j] * DD);
        ((float4*)(gout + (size_t)j * DD))[c] = src[c];
    }
}

// ---------------------------------------------------------------------------
extern "C" void kernel_launch(void* const* d_in, const int* in_sizes, int n_in,
                              void* d_out, int out_size) {
    const float* Q   = (const float*)d_in[0];
    const float* M   = (const float*)d_in[1];
    const float* imp = (const float*)d_in[2];
    float* out = (float*)d_out;

    cudaFuncSetAttribute(gemm_scan_kernel, cudaFuncAttributeMaxDynamicSharedMemorySize, GEMM_SMEM);

    prep_kernel<<<MBLKS + BB / 8, 256>>>(Q, M, imp);

    dim3 ggrid(BB / BM, NN / BN);   // (4, 1024)
    gemm_scan_kernel<<<ggrid, 128, GEMM_SMEM>>>();

    rescore_kernel<<<BB, 256>>>(Q, M, imp, out);
    fallback_kernel<<<BB, 256>>>(Q, M, imp, out);
}